// round 9
// baseline (speedup 1.0000x reference)
#include <cuda_runtime.h>
#include <cstdint>

#define NQ 50000

// ---------------- scratch (device globals; no allocation allowed) ----------------
__device__ float g_QKV[(size_t)NQ * 384];    // [Q | KF | VF] per row (biases folded)
__device__ float g_U[(size_t)NQ * 1024];     // u[n,h,c]
__device__ float g_PBAR[(size_t)NQ * 1024];  // pbar[n,h,c]
__device__ float g_CTX[(size_t)NQ * 128];
__device__ float g_X1[(size_t)NQ * 128];
__device__ float g_H1[(size_t)NQ * 256];
__device__ float g_T1[(size_t)NQ * 128];
__device__ float g_T2[(size_t)NQ * 128];
__device__ float4 g_WvT4[32 * 128];          // [c4][e]: Wv[e][4c4..4c4+3]

// ---------------- helpers ----------------
__device__ __forceinline__ float to_tf32(float x)
{
    uint32_t r;
    asm("cvt.rna.tf32.f32 %0, %1;" : "=r"(r) : "f"(x));
    return __uint_as_float(r);
}

// hi/lo split: x ~= hi + lo, both exactly representable in tf32
__device__ __forceinline__ float2 tf32_split(float x)
{
    float h = to_tf32(x);
    return make_float2(h, to_tf32(x - h));
}

__device__ __forceinline__ void mma_tf32(float* d, const uint32_t* a, const uint32_t* b)
{
    asm volatile(
        "mma.sync.aligned.m16n8k8.row.col.f32.tf32.tf32.f32 "
        "{%0,%1,%2,%3}, {%4,%5,%6,%7}, {%8,%9}, {%0,%1,%2,%3};"
        : "+f"(d[0]), "+f"(d[1]), "+f"(d[2]), "+f"(d[3])
        : "r"(a[0]), "r"(a[1]), "r"(a[2]), "r"(a[3]), "r"(b[0]), "r"(b[1]));
}

// ---------------- one-time weight repack (WvT4 only) ----------------
__global__ void prep_w(const float* __restrict__ ipw)
{
    const int c4 = blockIdx.x;      // 0..31
    const int e  = threadIdx.x;     // 0..127
    const float* p = ipw + (size_t)(256 + e) * 128 + 4 * c4;
    g_WvT4[c4 * 128 + e] = make_float4(p[0], p[1], p[2], p[3]);
}

// ---------------- 3xTF32 tensor-core GEMM: C = A[M,K] @ B[Nc,K]^T + bias ----------------
// CTA 128x64, 8 warps, warp tile 64x16 (4 m16 x 2 n8). fp32-level accuracy via hi/lo split.
__global__ __launch_bounds__(256) void sgemm_tf32(
    const float* __restrict__ A, const float* __restrict__ B,
    const float* __restrict__ bias, float* __restrict__ C,
    int M, int Nc, int K, int relu)
{
    __shared__ float2 As[16][132];   // [k][m] (hi, lo)
    __shared__ float2 Bs[16][68];    // [k][n] (hi, lo)
    const int tid = threadIdx.x;
    const int m0 = blockIdx.x * 128, n0 = blockIdx.y * 64;
    const int lane = tid & 31, wid = tid >> 5;
    const int wm = wid & 1, wn = wid >> 1;           // warp tile origin (wm*64, wn*16)
    const int gid = lane >> 2, tig = lane & 3;
    const int ar = tid & 127;          // A row in tile
    const int ak = (tid >> 7) * 8;     // A k offset (0 or 8)
    const int br = tid & 63;           // B row in tile
    const int bk = (tid >> 6) * 4;     // B k offset (0,4,8,12)
    const bool aval = (m0 + ar) < M;
    const float* Arow = A + (size_t)(m0 + ar) * K;
    const float* Brow = B + (size_t)(n0 + br) * K;

    float acc[4][2][4];
#pragma unroll
    for (int i = 0; i < 4; i++)
#pragma unroll
        for (int j = 0; j < 2; j++)
#pragma unroll
            for (int v = 0; v < 4; v++) acc[i][j][v] = 0.f;

    for (int k0 = 0; k0 < K; k0 += 16) {
        float4 a0 = make_float4(0.f, 0.f, 0.f, 0.f), a1 = a0;
        if (aval) {
            a0 = *(const float4*)(Arow + k0 + ak);
            a1 = *(const float4*)(Arow + k0 + ak + 4);
        }
        float4 b0 = *(const float4*)(Brow + k0 + bk);
        __syncthreads();
        As[ak + 0][ar] = tf32_split(a0.x); As[ak + 1][ar] = tf32_split(a0.y);
        As[ak + 2][ar] = tf32_split(a0.z); As[ak + 3][ar] = tf32_split(a0.w);
        As[ak + 4][ar] = tf32_split(a1.x); As[ak + 5][ar] = tf32_split(a1.y);
        As[ak + 6][ar] = tf32_split(a1.z); As[ak + 7][ar] = tf32_split(a1.w);
        Bs[bk + 0][br] = tf32_split(b0.x); Bs[bk + 1][br] = tf32_split(b0.y);
        Bs[bk + 2][br] = tf32_split(b0.z); Bs[bk + 3][br] = tf32_split(b0.w);
        __syncthreads();
#pragma unroll
        for (int ks = 0; ks < 16; ks += 8) {
            uint32_t bh[2][2], bl[2][2];
#pragma unroll
            for (int nt = 0; nt < 2; nt++) {
                float2 v0 = Bs[ks + tig][wn * 16 + nt * 8 + gid];
                float2 v1 = Bs[ks + tig + 4][wn * 16 + nt * 8 + gid];
                bh[nt][0] = __float_as_uint(v0.x); bl[nt][0] = __float_as_uint(v0.y);
                bh[nt][1] = __float_as_uint(v1.x); bl[nt][1] = __float_as_uint(v1.y);
            }
#pragma unroll
            for (int mt = 0; mt < 4; mt++) {
                const int mb = wm * 64 + mt * 16 + gid;
                float2 w0 = As[ks + tig][mb];
                float2 w1 = As[ks + tig][mb + 8];
                float2 w2 = As[ks + tig + 4][mb];
                float2 w3 = As[ks + tig + 4][mb + 8];
                uint32_t ah[4] = {__float_as_uint(w0.x), __float_as_uint(w1.x),
                                  __float_as_uint(w2.x), __float_as_uint(w3.x)};
                uint32_t al[4] = {__float_as_uint(w0.y), __float_as_uint(w1.y),
                                  __float_as_uint(w2.y), __float_as_uint(w3.y)};
#pragma unroll
                for (int nt = 0; nt < 2; nt++) {
                    mma_tf32(acc[mt][nt], al, bh[nt]);   // a_lo * b_hi
                    mma_tf32(acc[mt][nt], ah, bl[nt]);   // a_hi * b_lo
                    mma_tf32(acc[mt][nt], ah, bh[nt]);   // a_hi * b_hi
                }
            }
        }
    }

#pragma unroll
    for (int nt = 0; nt < 2; nt++) {
        const int col = n0 + wn * 16 + nt * 8 + tig * 2;
        const float bb0 = __ldg(bias + col), bb1 = __ldg(bias + col + 1);
#pragma unroll
        for (int mt = 0; mt < 4; mt++) {
            const int row0 = m0 + wm * 64 + mt * 16 + gid;
            const int row1 = row0 + 8;
            float d0 = acc[mt][nt][0] + bb0, d1 = acc[mt][nt][1] + bb1;
            float d2 = acc[mt][nt][2] + bb0, d3 = acc[mt][nt][3] + bb1;
            if (relu) {
                d0 = fmaxf(d0, 0.f); d1 = fmaxf(d1, 0.f);
                d2 = fmaxf(d2, 0.f); d3 = fmaxf(d3, 0.f);
            }
            if (row0 < M) *(float2*)(C + (size_t)row0 * Nc + col) = make_float2(d0, d1);
            if (row1 < M) *(float2*)(C + (size_t)row1 * Nc + col) = make_float2(d2, d3);
        }
    }
}

// ---------------- U gemm: U[n,h,c] = sum_d Q[n,16h+d]*Wk[16h+d,c]; Wk col in regs ----------------
__global__ __launch_bounds__(512) void u_gemm(const float* __restrict__ ipw)
{
    __shared__ float Qs[16][128];
    const int tid = threadIdx.x;
    const int c  = tid & 127;
    const int hg = tid >> 7;            // 0..3 -> heads {2hg, 2hg+1}
    float wk[2][16];
#pragma unroll
    for (int j = 0; j < 2; j++)
#pragma unroll
        for (int d = 0; d < 16; d++)
            wk[j][d] = ipw[(size_t)(128 + (2 * hg + j) * 16 + d) * 128 + c];
    const int n0 = blockIdx.x * 128;
    for (int qt = 0; qt < 8; qt++) {
        __syncthreads();
        {
            int i4 = tid;                       // float4 index 0..511
            int q = i4 >> 5, cc = (i4 & 31) * 4;
            int n = n0 + qt * 16 + q;
            float4 v = make_float4(0.f, 0.f, 0.f, 0.f);
            if (n < NQ) v = *(const float4*)&g_QKV[(size_t)n * 384 + cc];
            *(float4*)&Qs[q][cc] = v;
        }
        __syncthreads();
#pragma unroll 4
        for (int q = 0; q < 16; q++) {
            int n = n0 + qt * 16 + q;
            if (n >= NQ) break;
#pragma unroll
            for (int j = 0; j < 2; j++) {
                const int h = 2 * hg + j;
                float acc = 0.f;
#pragma unroll
                for (int d = 0; d < 16; d++)
                    acc = fmaf(Qs[q][h * 16 + d], wk[j][d], acc);
                g_U[(size_t)n * 1024 + h * 128 + c] = acc;
            }
        }
    }
}

// ---------------- lean fused attention with MLP-8 gather batches ----------------
struct AttnSmem {
    float PE[48][132];
    float U[8][128];
    float St[48][8];
    float SKF[48][8];
    float Rel[48][4];
    float Mskf[48];
    int   Idx[48];
};

__global__ __launch_bounds__(128) void attn_kernel(
    const float* __restrict__ coords,
    const int* __restrict__ kidx,
    const int* __restrict__ kmask,
    const float* __restrict__ kposw,
    const float* __restrict__ kposb)
{
    __shared__ AttnSmem sm;
    const int n = blockIdx.x;
    const int tid = threadIdx.x;       // 128
    const int h_self = tid >> 4;
    const int lane16 = tid & 15;

    const float w0 = kposw[tid * 3 + 0];
    const float w1 = kposw[tid * 3 + 1];
    const float w2 = kposw[tid * 3 + 2];
    const float pbias = kposb[tid];
    const float qv = g_QKV[(size_t)n * 384 + tid];   // my channel of q

#pragma unroll
    for (int h = 0; h < 8; h++)
        sm.U[h][tid] = g_U[(size_t)n * 1024 + h * 128 + tid];

    const float qx = coords[n * 3 + 0];
    const float qy = coords[n * 3 + 1];
    const float qz = coords[n * 3 + 2];
    if (tid < 48) {
        int idx = kidx[n * 48 + tid];
        sm.Idx[tid] = idx;
        sm.Mskf[tid] = (kmask[n * 48 + tid] != 0) ? -1e9f : 0.f;
        sm.Rel[tid][0] = coords[idx * 3 + 0] - qx;
        sm.Rel[tid][1] = coords[idx * 3 + 1] - qy;
        sm.Rel[tid][2] = coords[idx * 3 + 2] - qz;
        sm.Rel[tid][3] = 0.f;
    }
    __syncthreads();

    // gather KF (batch-8 LDG prefetch, shuffle-reduced q.kf) + pos-emb
    for (int kb0 = 0; kb0 < 48; kb0 += 8) {
        float kfr[8];
#pragma unroll
        for (int j = 0; j < 8; j++)
            kfr[j] = __ldcg(&g_QKV[(size_t)sm.Idx[kb0 + j] * 384 + 128 + tid]);
#pragma unroll
        for (int j = 0; j < 8; j++) {
            const int k = kb0 + j;
            float4 r = *(const float4*)&sm.Rel[k][0];
            sm.PE[k][tid] = fmaxf(fmaf(w0, r.x, fmaf(w1, r.y, fmaf(w2, r.z, pbias))), 0.f);
            float p = qv * kfr[j];                      // 16-lane group == head channels
            p += __shfl_xor_sync(0xffffffffu, p, 8, 16);
            p += __shfl_xor_sync(0xffffffffu, p, 4, 16);
            p += __shfl_xor_sync(0xffffffffu, p, 2, 16);
            p += __shfl_xor_sync(0xffffffffu, p, 1, 16);
            if (lane16 == 0) sm.SKF[k][h_self] = p;
        }
    }
    __syncthreads();

    // scores: thread (h_self, kb) handles k = kb, kb+16, kb+32 (u . pe part)
    {
        const int kb = lane16;
        float s0 = 0.f, s1 = 0.f, s2 = 0.f;
#pragma unroll 8
        for (int c4 = 0; c4 < 32; c4++) {
            float4 u  = *(const float4*)&sm.U[h_self][c4 * 4];
            float4 p0 = *(const float4*)&sm.PE[kb][c4 * 4];
            float4 p1 = *(const float4*)&sm.PE[kb + 16][c4 * 4];
            float4 p2 = *(const float4*)&sm.PE[kb + 32][c4 * 4];
            s0 += u.x * p0.x + u.y * p0.y + u.z * p0.z + u.w * p0.w;
            s1 += u.x * p1.x + u.y * p1.y + u.z * p1.z + u.w * p1.w;
            s2 += u.x * p2.x + u.y * p2.y + u.z * p2.z + u.w * p2.w;
        }
        sm.St[kb][h_self]      = fmaf(s0 + sm.SKF[kb][h_self],      0.25f, sm.Mskf[kb]);
        sm.St[kb + 16][h_self] = fmaf(s1 + sm.SKF[kb + 16][h_self], 0.25f, sm.Mskf[kb + 16]);
        sm.St[kb + 32][h_self] = fmaf(s2 + sm.SKF[kb + 32][h_self], 0.25f, sm.Mskf[kb + 32]);
    }
    __syncthreads();

    // softmax: 16 lanes per head
    {
        const int l = lane16;
        float v0 = sm.St[l][h_self], v1 = sm.St[l + 16][h_self], v2 = sm.St[l + 32][h_self];
        float m = fmaxf(v0, fmaxf(v1, v2));
#pragma unroll
        for (int o = 8; o; o >>= 1) m = fmaxf(m, __shfl_xor_sync(0xffffffffu, m, o, 16));
        float e0 = __expf(v0 - m), e1 = __expf(v1 - m), e2 = __expf(v2 - m);
        float s = e0 + e1 + e2;
#pragma unroll
        for (int o = 8; o; o >>= 1) s += __shfl_xor_sync(0xffffffffu, s, o, 16);
        float inv = 1.f / s;
        sm.St[l][h_self] = e0 * inv;
        sm.St[l + 16][h_self] = e1 * inv;
        sm.St[l + 32][h_self] = e2 * inv;
    }
    __syncthreads();

    // pbar (8 acc) + ctx_feat with batch-8 VF prefetch
    float pbv[8] = {0.f, 0.f, 0.f, 0.f, 0.f, 0.f, 0.f, 0.f};
    float ctx = 0.f;
    for (int kb0 = 0; kb0 < 48; kb0 += 8) {
        float vfr[8];
#pragma unroll
        for (int j = 0; j < 8; j++)
            vfr[j] = __ldcg(&g_QKV[(size_t)sm.Idx[kb0 + j] * 384 + 256 + tid]);
#pragma unroll
        for (int j = 0; j < 8; j++) {
            const int k = kb0 + j;
            float4 a0 = *(const float4*)&sm.St[k][0];
            float4 a1 = *(const float4*)&sm.St[k][4];
            float pe = sm.PE[k][tid];
            float aw = sm.St[k][h_self];
            pbv[0] = fmaf(a0.x, pe, pbv[0]); pbv[1] = fmaf(a0.y, pe, pbv[1]);
            pbv[2] = fmaf(a0.z, pe, pbv[2]); pbv[3] = fmaf(a0.w, pe, pbv[3]);
            pbv[4] = fmaf(a1.x, pe, pbv[4]); pbv[5] = fmaf(a1.y, pe, pbv[5]);
            pbv[6] = fmaf(a1.z, pe, pbv[6]); pbv[7] = fmaf(a1.w, pe, pbv[7]);
            ctx = fmaf(aw, vfr[j], ctx);
        }
    }
    g_CTX[(size_t)n * 128 + tid] = ctx;
#pragma unroll
    for (int h = 0; h < 8; h++)
        g_PBAR[(size_t)n * 1024 + h * 128 + tid] = pbv[h];
}

// ---------------- ctx += Wv.pbar : WvT4 L1-resident, w4 reused across 4 queries ----------------
__global__ __launch_bounds__(256) void ctxpos2()
{
    __shared__ float PBs[8][1024];
    const int tid = threadIdx.x;
    const int half = tid >> 7;          // 0/1 -> queries 0-3 / 4-7 of stage
    const int e = tid & 127;
    const int h = e >> 4;
    const int n0 = blockIdx.x * 64;
    for (int s = 0; s < 8; s++) {
        __syncthreads();
#pragma unroll
        for (int j = 0; j < 8; j++) {
            int i4 = tid + j * 256;             // float4 index 0..2047
            int q = i4 >> 8, cc = (i4 & 255) * 4;
            int n = n0 + s * 8 + q;
            float4 v = make_float4(0.f, 0.f, 0.f, 0.f);
            if (n < NQ) v = *(const float4*)&g_PBAR[(size_t)n * 1024 + cc];
            *(float4*)&PBs[q][cc] = v;
        }
        __syncthreads();
        float acc[4] = {0.f, 0.f, 0.f, 0.f};
#pragma unroll 8
        for (int c4 = 0; c4 < 32; c4++) {
            float4 w = __ldg(&g_WvT4[c4 * 128 + e]);
#pragma unroll
            for (int j = 0; j < 4; j++) {
                float4 p = *(const float4*)&PBs[half * 4 + j][h * 128 + c4 * 4];
                acc[j] += w.x * p.x + w.y * p.y + w.z * p.z + w.w * p.w;
            }
        }
#pragma unroll
        for (int j = 0; j < 4; j++) {
            int n = n0 + s * 8 + half * 4 + j;
            if (n < NQ) g_CTX[(size_t)n * 128 + e] += acc[j];
        }
    }
}

// ---------------- layernorm (optional residual, optional relu), C=128 ----------------
__global__ __launch_bounds__(256) void ln_kernel(
    const float* __restrict__ a, const float* __restrict__ b,
    const float* __restrict__ g, const float* __restrict__ bb,
    float* __restrict__ out, int relu)
{
    const int row = blockIdx.x * 8 + (threadIdx.x >> 5);
    const int lane = threadIdx.x & 31;
    if (row >= NQ) return;
    float4 x = ((const float4*)(a + (size_t)row * 128))[lane];
    if (b) {
        float4 y = ((const float4*)(b + (size_t)row * 128))[lane];
        x.x += y.x; x.y += y.y; x.z += y.z; x.w += y.w;
    }
    float s = x.x + x.y + x.z + x.w;
    float s2 = x.x * x.x + x.y * x.y + x.z * x.z + x.w * x.w;
#pragma unroll
    for (int o = 16; o; o >>= 1) {
        s += __shfl_xor_sync(0xffffffffu, s, o);
        s2 += __shfl_xor_sync(0xffffffffu, s2, o);
    }
    const float mean = s * (1.f / 128.f);
    const float var = s2 * (1.f / 128.f) - mean * mean;
    const float rstd = rsqrtf(var + 1e-5f);
    float4 gg = ((const float4*)g)[lane];
    float4 bv = ((const float4*)bb)[lane];
    float4 o4;
    o4.x = (x.x - mean) * rstd * gg.x + bv.x;
    o4.y = (x.y - mean) * rstd * gg.y + bv.y;
    o4.z = (x.z - mean) * rstd * gg.z + bv.z;
    o4.w = (x.w - mean) * rstd * gg.w + bv.w;
    if (relu) {
        o4.x = fmaxf(o4.x, 0.f); o4.y = fmaxf(o4.y, 0.f);
        o4.z = fmaxf(o4.z, 0.f); o4.w = fmaxf(o4.w, 0.f);
    }
    ((float4*)(out + (size_t)row * 128))[lane] = o4;
}

// ---------------- host launcher ----------------
extern "C" void kernel_launch(void* const* d_in, const int* in_sizes, int n_in,
                              void* d_out, int out_size)
{
    const float* vf     = (const float*)d_in[0];
    const float* coords = (const float*)d_in[1];
    const int*   kidx   = (const int*)d_in[2];
    const int*   kmask  = (const int*)d_in[3];
    const float* ipw  = (const float*)d_in[4];
    const float* ipb  = (const float*)d_in[5];
    const float* opw  = (const float*)d_in[6];
    const float* opb  = (const float*)d_in[7];
    const float* kpw  = (const float*)d_in[8];
    const float* kpb  = (const float*)d_in[9];
    const float* ln1g = (const float*)d_in[10];
    const float* ln1b = (const float*)d_in[11];
    const float* ln2g = (const float*)d_in[12];
    const float* ln2b = (const float*)d_in[13];
    const float* ff1w = (const float*)d_in[14];
    const float* ff1b = (const float*)d_in[15];
    const float* ff2w = (const float*)d_in[16];
    const float* ff2b = (const float*)d_in[17];
    const float* outw = (const float*)d_in[18];
    const float* outb = (const float*)d_in[19];
    const float* ln3g = (const float*)d_in[20];
    const float* ln3b = (const float*)d_in[21];
    float* out = (float*)d_out;
    (void)in_sizes; (void)n_in; (void)out_size;

    float *QKV, *CTX, *X1, *H1, *T1, *T2;
    cudaGetSymbolAddress((void**)&QKV, g_QKV);
    cudaGetSymbolAddress((void**)&CTX, g_CTX);
    cudaGetSymbolAddress((void**)&X1,  g_X1);
    cudaGetSymbolAddress((void**)&H1,  g_H1);
    cudaGetSymbolAddress((void**)&T1,  g_T1);
    cudaGetSymbolAddress((void**)&T2,  g_T2);

    const int MB = (NQ + 127) / 128;   // 391

    // 0. repack Wv^T into float4 table
    prep_w<<<32, 128>>>(ipw);
    // 1. QKV base projections (Q|KF|VF), biases folded  [3xTF32]
    sgemm_tf32<<<dim3(MB, 6), 256>>>(vf, ipw, ipb, QKV, NQ, 384, 128, 0);
    // 2. U = per-head q^T Wk (weight cols in registers)
    u_gemm<<<MB, 512>>>(ipw);
    // 3. lean fused attention -> g_CTX (feat part), g_PBAR
    attn_kernel<<<NQ, 128>>>(coords, kidx, kmask, kpw, kpb);
    // 4. g_CTX += Wv . pbar
    ctxpos2<<<(NQ + 63) / 64, 256>>>();
    // 5. attend = ctx @ out_proj^T + b  [3xTF32]
    sgemm_tf32<<<dim3(MB, 2), 256>>>(CTX, opw, opb, T1, NQ, 128, 128, 0);
    // 6. x1 = LN(vf + attend)
    ln_kernel<<<(NQ + 7) / 8, 256>>>(vf, T1, ln1g, ln1b, X1, 0);
    // 7. h = relu(x1 @ ff1^T + b)  [3xTF32]
    sgemm_tf32<<<dim3(MB, 4), 256>>>(X1, ff1w, ff1b, H1, NQ, 256, 128, 1);
    // 8. ff = h @ ff2^T + b  [3xTF32]
    sgemm_tf32<<<dim3(MB, 2), 256>>>(H1, ff2w, ff2b, T1, NQ, 128, 256, 0);
    // 9. x2 = LN(x1 + ff)
    ln_kernel<<<(NQ + 7) / 8, 256>>>(X1, T1, ln2g, ln2b, T2, 0);
    // 10. o = x2 @ out_w^T + b  [3xTF32]
    sgemm_tf32<<<dim3(MB, 2), 256>>>(T2, outw, outb, T1, NQ, 128, 128, 0);
    // 11. out = relu(LN(o))
    ln_kernel<<<(NQ + 7) / 8, 256>>>(T1, nullptr, ln3g, ln3b, out, 1);
}

// round 10
// speedup vs baseline: 1.0032x; 1.0032x over previous
#include <cuda_runtime.h>
#include <cstdint>

#define NQ 50000

// ---------------- scratch (device globals; no allocation allowed) ----------------
__device__ float g_QKV[(size_t)NQ * 384];    // [Q | KF | VF] per row (biases folded)
__device__ float g_U[(size_t)NQ * 1024];     // u[n,h,c]
__device__ float g_PBAR[(size_t)NQ * 1024];  // pbar[n,h,c]
__device__ float g_CTX[(size_t)NQ * 128];
__device__ float g_X1[(size_t)NQ * 128];
__device__ float g_H1[(size_t)NQ * 256];
__device__ float g_T1[(size_t)NQ * 128];
__device__ float g_T2[(size_t)NQ * 128];
__device__ float4 g_WvT4[32 * 128];          // [c4][e]: Wv[e][4c4..4c4+3]

// ---------------- helpers ----------------
__device__ __forceinline__ float to_tf32(float x)
{
    uint32_t r;
    asm("cvt.rna.tf32.f32 %0, %1;" : "=r"(r) : "f"(x));
    return __uint_as_float(r);
}

// hi/lo split: x ~= hi + lo, both exactly representable in tf32
__device__ __forceinline__ float2 tf32_split(float x)
{
    float h = to_tf32(x);
    return make_float2(h, to_tf32(x - h));
}

__device__ __forceinline__ void mma_tf32(float* d, const uint32_t* a, const uint32_t* b)
{
    asm volatile(
        "mma.sync.aligned.m16n8k8.row.col.f32.tf32.tf32.f32 "
        "{%0,%1,%2,%3}, {%4,%5,%6,%7}, {%8,%9}, {%0,%1,%2,%3};"
        : "+f"(d[0]), "+f"(d[1]), "+f"(d[2]), "+f"(d[3])
        : "r"(a[0]), "r"(a[1]), "r"(a[2]), "r"(a[3]), "r"(b[0]), "r"(b[1]));
}

// ---------------- one-time weight repack (WvT4 only) ----------------
__global__ void prep_w(const float* __restrict__ ipw)
{
    const int c4 = blockIdx.x;      // 0..31
    const int e  = threadIdx.x;     // 0..127
    const float* p = ipw + (size_t)(256 + e) * 128 + 4 * c4;
    g_WvT4[c4 * 128 + e] = make_float4(p[0], p[1], p[2], p[3]);
}

// ---------------- 3xTF32 tensor-core GEMM: C = A[M,K] @ B[Nc,K]^T + bias ----------------
// CTA 128x64, 8 warps, warp tile 64x16 (4 m16 x 2 n8). fp32-level accuracy via hi/lo split.
__global__ __launch_bounds__(256) void sgemm_tf32(
    const float* __restrict__ A, const float* __restrict__ B,
    const float* __restrict__ bias, float* __restrict__ C,
    int M, int Nc, int K, int relu)
{
    __shared__ float2 As[16][132];   // [k][m] (hi, lo)
    __shared__ float2 Bs[16][68];    // [k][n] (hi, lo)
    const int tid = threadIdx.x;
    const int m0 = blockIdx.x * 128, n0 = blockIdx.y * 64;
    const int lane = tid & 31, wid = tid >> 5;
    const int wm = wid & 1, wn = wid >> 1;           // warp tile origin (wm*64, wn*16)
    const int gid = lane >> 2, tig = lane & 3;
    const int ar = tid & 127;          // A row in tile
    const int ak = (tid >> 7) * 8;     // A k offset (0 or 8)
    const int br = tid & 63;           // B row in tile
    const int bk = (tid >> 6) * 4;     // B k offset (0,4,8,12)
    const bool aval = (m0 + ar) < M;
    const float* Arow = A + (size_t)(m0 + ar) * K;
    const float* Brow = B + (size_t)(n0 + br) * K;

    float acc[4][2][4];
#pragma unroll
    for (int i = 0; i < 4; i++)
#pragma unroll
        for (int j = 0; j < 2; j++)
#pragma unroll
            for (int v = 0; v < 4; v++) acc[i][j][v] = 0.f;

    for (int k0 = 0; k0 < K; k0 += 16) {
        float4 a0 = make_float4(0.f, 0.f, 0.f, 0.f), a1 = a0;
        if (aval) {
            a0 = *(const float4*)(Arow + k0 + ak);
            a1 = *(const float4*)(Arow + k0 + ak + 4);
        }
        float4 b0 = *(const float4*)(Brow + k0 + bk);
        __syncthreads();
        As[ak + 0][ar] = tf32_split(a0.x); As[ak + 1][ar] = tf32_split(a0.y);
        As[ak + 2][ar] = tf32_split(a0.z); As[ak + 3][ar] = tf32_split(a0.w);
        As[ak + 4][ar] = tf32_split(a1.x); As[ak + 5][ar] = tf32_split(a1.y);
        As[ak + 6][ar] = tf32_split(a1.z); As[ak + 7][ar] = tf32_split(a1.w);
        Bs[bk + 0][br] = tf32_split(b0.x); Bs[bk + 1][br] = tf32_split(b0.y);
        Bs[bk + 2][br] = tf32_split(b0.z); Bs[bk + 3][br] = tf32_split(b0.w);
        __syncthreads();
#pragma unroll
        for (int ks = 0; ks < 16; ks += 8) {
            uint32_t bh[2][2], bl[2][2];
#pragma unroll
            for (int nt = 0; nt < 2; nt++) {
                float2 v0 = Bs[ks + tig][wn * 16 + nt * 8 + gid];
                float2 v1 = Bs[ks + tig + 4][wn * 16 + nt * 8 + gid];
                bh[nt][0] = __float_as_uint(v0.x); bl[nt][0] = __float_as_uint(v0.y);
                bh[nt][1] = __float_as_uint(v1.x); bl[nt][1] = __float_as_uint(v1.y);
            }
#pragma unroll
            for (int mt = 0; mt < 4; mt++) {
                const int mb = wm * 64 + mt * 16 + gid;
                float2 w0 = As[ks + tig][mb];
                float2 w1 = As[ks + tig][mb + 8];
                float2 w2 = As[ks + tig + 4][mb];
                float2 w3 = As[ks + tig + 4][mb + 8];
                uint32_t ah[4] = {__float_as_uint(w0.x), __float_as_uint(w1.x),
                                  __float_as_uint(w2.x), __float_as_uint(w3.x)};
                uint32_t al[4] = {__float_as_uint(w0.y), __float_as_uint(w1.y),
                                  __float_as_uint(w2.y), __float_as_uint(w3.y)};
#pragma unroll
                for (int nt = 0; nt < 2; nt++) {
                    mma_tf32(acc[mt][nt], al, bh[nt]);   // a_lo * b_hi
                    mma_tf32(acc[mt][nt], ah, bl[nt]);   // a_hi * b_lo
                    mma_tf32(acc[mt][nt], ah, bh[nt]);   // a_hi * b_hi
                }
            }
        }
    }

#pragma unroll
    for (int nt = 0; nt < 2; nt++) {
        const int col = n0 + wn * 16 + nt * 8 + tig * 2;
        const float bb0 = __ldg(bias + col), bb1 = __ldg(bias + col + 1);
#pragma unroll
        for (int mt = 0; mt < 4; mt++) {
            const int row0 = m0 + wm * 64 + mt * 16 + gid;
            const int row1 = row0 + 8;
            float d0 = acc[mt][nt][0] + bb0, d1 = acc[mt][nt][1] + bb1;
            float d2 = acc[mt][nt][2] + bb0, d3 = acc[mt][nt][3] + bb1;
            if (relu) {
                d0 = fmaxf(d0, 0.f); d1 = fmaxf(d1, 0.f);
                d2 = fmaxf(d2, 0.f); d3 = fmaxf(d3, 0.f);
            }
            if (row0 < M) *(float2*)(C + (size_t)row0 * Nc + col) = make_float2(d0, d1);
            if (row1 < M) *(float2*)(C + (size_t)row1 * Nc + col) = make_float2(d2, d3);
        }
    }
}

// ---------------- U gemm: U[n,h,c] = sum_d Q[n,16h+d]*Wk[16h+d,c]; Wk col in regs ----------------
__global__ __launch_bounds__(512) void u_gemm(const float* __restrict__ ipw)
{
    __shared__ float Qs[16][128];
    const int tid = threadIdx.x;
    const int c  = tid & 127;
    const int hg = tid >> 7;            // 0..3 -> heads {2hg, 2hg+1}
    float wk[2][16];
#pragma unroll
    for (int j = 0; j < 2; j++)
#pragma unroll
        for (int d = 0; d < 16; d++)
            wk[j][d] = ipw[(size_t)(128 + (2 * hg + j) * 16 + d) * 128 + c];
    const int n0 = blockIdx.x * 128;
    for (int qt = 0; qt < 8; qt++) {
        __syncthreads();
        {
            int i4 = tid;                       // float4 index 0..511
            int q = i4 >> 5, cc = (i4 & 31) * 4;
            int n = n0 + qt * 16 + q;
            float4 v = make_float4(0.f, 0.f, 0.f, 0.f);
            if (n < NQ) v = *(const float4*)&g_QKV[(size_t)n * 384 + cc];
            *(float4*)&Qs[q][cc] = v;
        }
        __syncthreads();
#pragma unroll 4
        for (int q = 0; q < 16; q++) {
            int n = n0 + qt * 16 + q;
            if (n >= NQ) break;
#pragma unroll
            for (int j = 0; j < 2; j++) {
                const int h = 2 * hg + j;
                float acc = 0.f;
#pragma unroll
                for (int d = 0; d < 16; d++)
                    acc = fmaf(Qs[q][h * 16 + d], wk[j][d], acc);
                g_U[(size_t)n * 1024 + h * 128 + c] = acc;
            }
        }
    }
}

// ---------------- lean fused attention with MLP-8 gather batches ----------------
struct AttnSmem {
    float PE[48][132];
    float U[8][128];
    float St[48][8];
    float SKF[48][8];
    float Rel[48][4];
    float Mskf[48];
    int   Idx[48];
};

__global__ __launch_bounds__(128) void attn_kernel(
    const float* __restrict__ coords,
    const int* __restrict__ kidx,
    const int* __restrict__ kmask,
    const float* __restrict__ kposw,
    const float* __restrict__ kposb)
{
    __shared__ AttnSmem sm;
    const int n = blockIdx.x;
    const int tid = threadIdx.x;       // 128
    const int h_self = tid >> 4;
    const int lane16 = tid & 15;

    const float w0 = kposw[tid * 3 + 0];
    const float w1 = kposw[tid * 3 + 1];
    const float w2 = kposw[tid * 3 + 2];
    const float pbias = kposb[tid];
    const float qv = g_QKV[(size_t)n * 384 + tid];   // my channel of q

#pragma unroll
    for (int h = 0; h < 8; h++)
        sm.U[h][tid] = g_U[(size_t)n * 1024 + h * 128 + tid];

    const float qx = coords[n * 3 + 0];
    const float qy = coords[n * 3 + 1];
    const float qz = coords[n * 3 + 2];
    if (tid < 48) {
        int idx = kidx[n * 48 + tid];
        sm.Idx[tid] = idx;
        sm.Mskf[tid] = (kmask[n * 48 + tid] != 0) ? -1e9f : 0.f;
        sm.Rel[tid][0] = coords[idx * 3 + 0] - qx;
        sm.Rel[tid][1] = coords[idx * 3 + 1] - qy;
        sm.Rel[tid][2] = coords[idx * 3 + 2] - qz;
        sm.Rel[tid][3] = 0.f;
    }
    __syncthreads();

    // gather KF (batch-8 LDG prefetch, shuffle-reduced q.kf) + pos-emb
    for (int kb0 = 0; kb0 < 48; kb0 += 8) {
        float kfr[8];
#pragma unroll
        for (int j = 0; j < 8; j++)
            kfr[j] = __ldcg(&g_QKV[(size_t)sm.Idx[kb0 + j] * 384 + 128 + tid]);
#pragma unroll
        for (int j = 0; j < 8; j++) {
            const int k = kb0 + j;
            float4 r = *(const float4*)&sm.Rel[k][0];
            sm.PE[k][tid] = fmaxf(fmaf(w0, r.x, fmaf(w1, r.y, fmaf(w2, r.z, pbias))), 0.f);
            float p = qv * kfr[j];                      // 16-lane group == head channels
            p += __shfl_xor_sync(0xffffffffu, p, 8, 16);
            p += __shfl_xor_sync(0xffffffffu, p, 4, 16);
            p += __shfl_xor_sync(0xffffffffu, p, 2, 16);
            p += __shfl_xor_sync(0xffffffffu, p, 1, 16);
            if (lane16 == 0) sm.SKF[k][h_self] = p;
        }
    }
    __syncthreads();

    // scores: thread (h_self, kb) handles k = kb, kb+16, kb+32 (u . pe part)
    {
        const int kb = lane16;
        float s0 = 0.f, s1 = 0.f, s2 = 0.f;
#pragma unroll 8
        for (int c4 = 0; c4 < 32; c4++) {
            float4 u  = *(const float4*)&sm.U[h_self][c4 * 4];
            float4 p0 = *(const float4*)&sm.PE[kb][c4 * 4];
            float4 p1 = *(const float4*)&sm.PE[kb + 16][c4 * 4];
            float4 p2 = *(const float4*)&sm.PE[kb + 32][c4 * 4];
            s0 += u.x * p0.x + u.y * p0.y + u.z * p0.z + u.w * p0.w;
            s1 += u.x * p1.x + u.y * p1.y + u.z * p1.z + u.w * p1.w;
            s2 += u.x * p2.x + u.y * p2.y + u.z * p2.z + u.w * p2.w;
        }
        sm.St[kb][h_self]      = fmaf(s0 + sm.SKF[kb][h_self],      0.25f, sm.Mskf[kb]);
        sm.St[kb + 16][h_self] = fmaf(s1 + sm.SKF[kb + 16][h_self], 0.25f, sm.Mskf[kb + 16]);
        sm.St[kb + 32][h_self] = fmaf(s2 + sm.SKF[kb + 32][h_self], 0.25f, sm.Mskf[kb + 32]);
    }
    __syncthreads();

    // softmax: 16 lanes per head
    {
        const int l = lane16;
        float v0 = sm.St[l][h_self], v1 = sm.St[l + 16][h_self], v2 = sm.St[l + 32][h_self];
        float m = fmaxf(v0, fmaxf(v1, v2));
#pragma unroll
        for (int o = 8; o; o >>= 1) m = fmaxf(m, __shfl_xor_sync(0xffffffffu, m, o, 16));
        float e0 = __expf(v0 - m), e1 = __expf(v1 - m), e2 = __expf(v2 - m);
        float s = e0 + e1 + e2;
#pragma unroll
        for (int o = 8; o; o >>= 1) s += __shfl_xor_sync(0xffffffffu, s, o, 16);
        float inv = 1.f / s;
        sm.St[l][h_self] = e0 * inv;
        sm.St[l + 16][h_self] = e1 * inv;
        sm.St[l + 32][h_self] = e2 * inv;
    }
    __syncthreads();

    // pbar (8 acc) + ctx_feat with batch-8 VF prefetch
    float pbv[8] = {0.f, 0.f, 0.f, 0.f, 0.f, 0.f, 0.f, 0.f};
    float ctx = 0.f;
    for (int kb0 = 0; kb0 < 48; kb0 += 8) {
        float vfr[8];
#pragma unroll
        for (int j = 0; j < 8; j++)
            vfr[j] = __ldcg(&g_QKV[(size_t)sm.Idx[kb0 + j] * 384 + 256 + tid]);
#pragma unroll
        for (int j = 0; j < 8; j++) {
            const int k = kb0 + j;
            float4 a0 = *(const float4*)&sm.St[k][0];
            float4 a1 = *(const float4*)&sm.St[k][4];
            float pe = sm.PE[k][tid];
            float aw = sm.St[k][h_self];
            pbv[0] = fmaf(a0.x, pe, pbv[0]); pbv[1] = fmaf(a0.y, pe, pbv[1]);
            pbv[2] = fmaf(a0.z, pe, pbv[2]); pbv[3] = fmaf(a0.w, pe, pbv[3]);
            pbv[4] = fmaf(a1.x, pe, pbv[4]); pbv[5] = fmaf(a1.y, pe, pbv[5]);
            pbv[6] = fmaf(a1.z, pe, pbv[6]); pbv[7] = fmaf(a1.w, pe, pbv[7]);
            ctx = fmaf(aw, vfr[j], ctx);
        }
    }
    g_CTX[(size_t)n * 128 + tid] = ctx;
#pragma unroll
    for (int h = 0; h < 8; h++)
        g_PBAR[(size_t)n * 1024 + h * 128 + tid] = pbv[h];
}

// ---------------- ctx += Wv.pbar : WvT4 L1-resident, w4 reused across 4 queries ----------------
__global__ __launch_bounds__(256) void ctxpos2()
{
    __shared__ float PBs[8][1024];
    const int tid = threadIdx.x;
    const int half = tid >> 7;          // 0/1 -> queries 0-3 / 4-7 of stage
    const int e = tid & 127;
    const int h = e >> 4;
    const int n0 = blockIdx.x * 64;
    for (int s = 0; s < 8; s++) {
        __syncthreads();
#pragma unroll
        for (int j = 0; j < 8; j++) {
            int i4 = tid + j * 256;             // float4 index 0..2047
            int q = i4 >> 8, cc = (i4 & 255) * 4;
            int n = n0 + s * 8 + q;
            float4 v = make_float4(0.f, 0.f, 0.f, 0.f);
            if (n < NQ) v = *(const float4*)&g_PBAR[(size_t)n * 1024 + cc];
            *(float4*)&PBs[q][cc] = v;
        }
        __syncthreads();
        float acc[4] = {0.f, 0.f, 0.f, 0.f};
#pragma unroll 8
        for (int c4 = 0; c4 < 32; c4++) {
            float4 w = __ldg(&g_WvT4[c4 * 128 + e]);
#pragma unroll
            for (int j = 0; j < 4; j++) {
                float4 p = *(const float4*)&PBs[half * 4 + j][h * 128 + c4 * 4];
                acc[j] += w.x * p.x + w.y * p.y + w.z * p.z + w.w * p.w;
            }
        }
#pragma unroll
        for (int j = 0; j < 4; j++) {
            int n = n0 + s * 8 + half * 4 + j;
            if (n < NQ) g_CTX[(size_t)n * 128 + e] += acc[j];
        }
    }
}

// ---------------- layernorm (optional residual, optional relu), C=128 ----------------
__global__ __launch_bounds__(256) void ln_kernel(
    const float* __restrict__ a, const float* __restrict__ b,
    const float* __restrict__ g, const float* __restrict__ bb,
    float* __restrict__ out, int relu)
{
    const int row = blockIdx.x * 8 + (threadIdx.x >> 5);
    const int lane = threadIdx.x & 31;
    if (row >= NQ) return;
    float4 x = ((const float4*)(a + (size_t)row * 128))[lane];
    if (b) {
        float4 y = ((const float4*)(b + (size_t)row * 128))[lane];
        x.x += y.x; x.y += y.y; x.z += y.z; x.w += y.w;
    }
    float s = x.x + x.y + x.z + x.w;
    float s2 = x.x * x.x + x.y * x.y + x.z * x.z + x.w * x.w;
#pragma unroll
    for (int o = 16; o; o >>= 1) {
        s += __shfl_xor_sync(0xffffffffu, s, o);
        s2 += __shfl_xor_sync(0xffffffffu, s2, o);
    }
    const float mean = s * (1.f / 128.f);
    const float var = s2 * (1.f / 128.f) - mean * mean;
    const float rstd = rsqrtf(var + 1e-5f);
    float4 gg = ((const float4*)g)[lane];
    float4 bv = ((const float4*)bb)[lane];
    float4 o4;
    o4.x = (x.x - mean) * rstd * gg.x + bv.x;
    o4.y = (x.y - mean) * rstd * gg.y + bv.y;
    o4.z = (x.z - mean) * rstd * gg.z + bv.z;
    o4.w = (x.w - mean) * rstd * gg.w + bv.w;
    if (relu) {
        o4.x = fmaxf(o4.x, 0.f); o4.y = fmaxf(o4.y, 0.f);
        o4.z = fmaxf(o4.z, 0.f); o4.w = fmaxf(o4.w, 0.f);
    }
    ((float4*)(out + (size_t)row * 128))[lane] = o4;
}

// ---------------- host launcher ----------------
extern "C" void kernel_launch(void* const* d_in, const int* in_sizes, int n_in,
                              void* d_out, int out_size)
{
    const float* vf     = (const float*)d_in[0];
    const float* coords = (const float*)d_in[1];
    const int*   kidx   = (const int*)d_in[2];
    const int*   kmask  = (const int*)d_in[3];
    const float* ipw  = (const float*)d_in[4];
    const float* ipb  = (const float*)d_in[5];
    const float* opw  = (const float*)d_in[6];
    const float* opb  = (const float*)d_in[7];
    const float* kpw  = (const float*)d_in[8];
    const float* kpb  = (const float*)d_in[9];
    const float* ln1g = (const float*)d_in[10];
    const float* ln1b = (const float*)d_in[11];
    const float* ln2g = (const float*)d_in[12];
    const float* ln2b = (const float*)d_in[13];
    const float* ff1w = (const float*)d_in[14];
    const float* ff1b = (const float*)d_in[15];
    const float* ff2w = (const float*)d_in[16];
    const float* ff2b = (const float*)d_in[17];
    const float* outw = (const float*)d_in[18];
    const float* outb = (const float*)d_in[19];
    const float* ln3g = (const float*)d_in[20];
    const float* ln3b = (const float*)d_in[21];
    float* out = (float*)d_out;
    (void)in_sizes; (void)n_in; (void)out_size;

    float *QKV, *CTX, *X1, *H1, *T1, *T2;
    cudaGetSymbolAddress((void**)&QKV, g_QKV);
    cudaGetSymbolAddress((void**)&CTX, g_CTX);
    cudaGetSymbolAddress((void**)&X1,  g_X1);
    cudaGetSymbolAddress((void**)&H1,  g_H1);
    cudaGetSymbolAddress((void**)&T1,  g_T1);
    cudaGetSymbolAddress((void**)&T2,  g_T2);

    const int MB = (NQ + 127) / 128;   // 391

    // 0. repack Wv^T into float4 table
    prep_w<<<32, 128>>>(ipw);
    // 1. QKV base projections (Q|KF|VF), biases folded  [3xTF32]
    sgemm_tf32<<<dim3(MB, 6), 256>>>(vf, ipw, ipb, QKV, NQ, 384, 128, 0);
    // 2. U = per-head q^T Wk (weight cols in registers)
    u_gemm<<<MB, 512>>>(ipw);
    // 3. lean fused attention -> g_CTX (feat part), g_PBAR
    attn_kernel<<<NQ, 128>>>(coords, kidx, kmask, kpw, kpb);
    // 4. g_CTX += Wv . pbar
    ctxpos2<<<(NQ + 63) / 64, 256>>>();
    // 5. attend = ctx @ out_proj^T + b  [3xTF32]
    sgemm_tf32<<<dim3(MB, 2), 256>>>(CTX, opw, opb, T1, NQ, 128, 128, 0);
    // 6. x1 = LN(vf + attend)
    ln_kernel<<<(NQ + 7) / 8, 256>>>(vf, T1, ln1g, ln1b, X1, 0);
    // 7. h = relu(x1 @ ff1^T + b)  [3xTF32]
    sgemm_tf32<<<dim3(MB, 4), 256>>>(X1, ff1w, ff1b, H1, NQ, 256, 128, 1);
    // 8. ff = h @ ff2^T + b  [3xTF32]
    sgemm_tf32<<<dim3(MB, 2), 256>>>(H1, ff2w, ff2b, T1, NQ, 128, 256, 0);
    // 9. x2 = LN(x1 + ff)
    ln_kernel<<<(NQ + 7) / 8, 256>>>(X1, T1, ln2g, ln2b, T2, 0);
    // 10. o = x2 @ out_w^T + b  [3xTF32]
    sgemm_tf32<<<dim3(MB, 2), 256>>>(T2, outw, outb, T1, NQ, 128, 128, 0);
    // 11. out = relu(LN(o))
    ln_kernel<<<(NQ + 7) / 8, 256>>>(T1, nullptr, ln3g, ln3b, out, 1);
}